// round 6
// baseline (speedup 1.0000x reference)
#include <cuda_runtime.h>

#define IMG_H 1024
#define IMG_W 768
#define IMG_C 3
#define IMG_HW (IMG_H * IMG_W)
#define ROW_F (IMG_W * IMG_C)          // 2304 floats per image row (mod 8 == 0)

// 256-bit global load (sm_100 family): 8 consecutive floats from a 32B-aligned ptr.
__device__ __forceinline__ void ldg256(const float* __restrict__ p, float r[8]) {
    unsigned a0, a1, a2, a3, a4, a5, a6, a7;
    asm("ld.global.nc.v8.b32 {%0,%1,%2,%3,%4,%5,%6,%7}, [%8];"
        : "=r"(a0), "=r"(a1), "=r"(a2), "=r"(a3),
          "=r"(a4), "=r"(a5), "=r"(a6), "=r"(a7)
        : "l"(p));
    r[0] = __uint_as_float(a0); r[1] = __uint_as_float(a1);
    r[2] = __uint_as_float(a2); r[3] = __uint_as_float(a3);
    r[4] = __uint_as_float(a4); r[5] = __uint_as_float(a5);
    r[6] = __uint_as_float(a6); r[7] = __uint_as_float(a7);
}

// branchless 4-way select by o in {0,1,2,3}
__device__ __forceinline__ float sel4(float a, float b, float c, float d, int o) {
    float r = (o == 1) ? b : a;
    r = (o == 2) ? c : r;
    r = (o == 3) ? d : r;
    return r;
}

__global__ __launch_bounds__(256) void warp_kernel(
    const float* __restrict__ image,
    const float* __restrict__ flow,
    float* __restrict__ out)
{
    int idx = blockIdx.x * 256 + threadIdx.x;  // one pixel per thread, exact grid

    int b   = idx / IMG_HW;
    int rem = idx - b * IMG_HW;
    int y   = rem / IMG_W;
    int x   = rem - y * IMG_W;

    float2 f = __ldg((const float2*)flow + idx);   // coalesced LDG.64
    float qy = (float)y - f.x;
    float qx = (float)x - f.y;

    float y0f = fminf(fmaxf(floorf(qy), 0.0f), (float)(IMG_H - 2));
    float x0f = fminf(fmaxf(floorf(qx), 0.0f), (float)(IMG_W - 2));
    float ay  = fminf(fmaxf(qy - y0f, 0.0f), 1.0f);
    float ax  = fminf(fmaxf(qx - x0f, 0.0f), 1.0f);

    int yi = (int)y0f;
    int xi = (int)x0f;

    const float* imgb = image + (size_t)b * (IMG_HW * IMG_C);
    int af = (yi * IMG_W + xi) * IMG_C;   // float offset of top-left sample
    int o8 = af & 7;                      // phase within 32B window (rows share it)

    const float* pt = imgb + (af & ~7);   // 32B-aligned top window
    const float* pb = pt + ROW_F;         // bottom window, same phase

    float t[13], bo[13];
    ldg256(pt, t);                        // floats 0..7 (one request each)
    ldg256(pb, bo);

    t[8] = t[9] = t[10] = t[11] = 0.0f;
    bo[8] = bo[9] = bo[10] = bo[11] = 0.0f;
    if (o8 >= 3) {                        // predicated tail: floats 8..11
        float4 tt = __ldg((const float4*)(pt + 8));
        float4 bb = __ldg((const float4*)(pb + 8));
        t[8] = tt.x;  t[9] = tt.y;  t[10] = tt.z;  t[11] = tt.w;
        bo[8] = bb.x; bo[9] = bb.y; bo[10] = bb.z; bo[11] = bb.w;
    }
    t[12] = bo[12] = 0.0f;
    if (o8 == 7) {                        // rare: span needs float 12 (in-bounds)
        t[12]  = __ldg(pt + 12);
        bo[12] = __ldg(pb + 12);
    }

    // vertical lerp: floats 0..7 always needed
    float m[13];
    #pragma unroll
    for (int j = 0; j < 8; j++)
        m[j] = t[j] + ay * (bo[j] - t[j]);
    // tail lerp only matters when o8>=3 (values are zero otherwise anyway,
    // but keep it unconditional-cheap: 5 FMA pairs)
    #pragma unroll
    for (int j = 8; j < 13; j++)
        m[j] = t[j] + ay * (bo[j] - t[j]);

    // stage 1: shift window by 4 if o8 >= 4
    float u[9];
    bool hi = (o8 >= 4);
    #pragma unroll
    for (int j = 0; j < 9; j++)
        u[j] = hi ? m[j + 4] : m[j];

    // stage 2: select span floats u[o2 + c] / u[o2 + 3 + c], horizontal lerp
    int o2 = o8 & 3;
    float l0 = sel4(u[0], u[1], u[2], u[3], o2);
    float l1 = sel4(u[1], u[2], u[3], u[4], o2);
    float l2 = sel4(u[2], u[3], u[4], u[5], o2);
    float r0 = sel4(u[3], u[4], u[5], u[6], o2);
    float r1 = sel4(u[4], u[5], u[6], u[7], o2);
    float r2 = sel4(u[5], u[6], u[7], u[8], o2);

    // direct scalar stores: 3 requests x 3 lines each per warp, no barrier
    float* op = out + (size_t)idx * 3;
    op[0] = l0 + ax * (r0 - l0);
    op[1] = l1 + ax * (r1 - l1);
    op[2] = l2 + ax * (r2 - l2);
}

extern "C" void kernel_launch(void* const* d_in, const int* in_sizes, int n_in,
                              void* d_out, int out_size) {
    const float* image = (const float*)d_in[0];
    const float* flow  = (const float*)d_in[1];
    float* out = (float*)d_out;

    int npix   = in_sizes[1] / 2;        // 18,874,368 — divisible by 256
    int blocks = npix / 256;             // 73728, no tail
    warp_kernel<<<blocks, 256>>>(image, flow, out);
}